// round 13
// baseline (speedup 1.0000x reference)
#include <cuda_runtime.h>

#define NB 8
#define NN 2048
#define NH 128
#define EPSF 1e-8f

typedef unsigned long long u64;

// Scratch (static __device__ globals — no allocations allowed)
__device__ float g_inv[2][NB * NN];        // per-row 1/max(||h||, eps)
__device__ float g_M[2][NB][NH * NH];      // g_M[t][b][l*128+k] = sum_m inv_t[m]*h_t[m,l]*h_t[m,k]
__device__ float g_W2T[NH * NH];           // g_W2T[l*128+k] = w_m[k,l]^2

// ---- packed f32x2 helpers (sm_100+): 2 IEEE fp32 FMAs per instruction ----
__device__ __forceinline__ u64 bcast2(float v) {
    unsigned u = __float_as_uint(v);
    u64 p;
    asm("mov.b64 %0, {%1, %2};" : "=l"(p) : "r"(u), "r"(u));
    return p;
}
__device__ __forceinline__ void fma2(u64& acc, u64 a, u64 b) {
    asm("fma.rn.f32x2 %0, %1, %2, %0;" : "+l"(acc) : "l"(a), "l"(b));
}
__device__ __forceinline__ void unpack2(u64 p, float& lo, float& hi) {
    unsigned a, b;
    asm("mov.b64 {%0, %1}, %2;" : "=r"(a), "=r"(b) : "l"(p));
    lo = __uint_as_float(a); hi = __uint_as_float(b);
}

// ------------------------------------------------------------------
// prep: inverse norms (blocks 0..4095), W2^T (4096..4159), zero M (4160..4415)
// ------------------------------------------------------------------
__global__ __launch_bounds__(256) void prep_kernel(
    const float* __restrict__ h1, const float* __restrict__ h2,
    const float* __restrict__ wm)
{
    int blk = blockIdx.x;
    if (blk < 4096) {
        int warp = threadIdx.x >> 5, lane = threadIdx.x & 31;
        int row = blk * 8 + warp;              // 0..32767
        int t = row >> 14;                      // 0: h1, 1: h2
        int idx = row & 16383;
        const float* src = t ? h2 : h1;
        float4 v = ((const float4*)(src + (size_t)idx * NH))[lane];
        float ss = v.x * v.x + v.y * v.y + v.z * v.z + v.w * v.w;
        #pragma unroll
        for (int o = 16; o; o >>= 1) ss += __shfl_xor_sync(0xffffffffu, ss, o);
        if (lane == 0) g_inv[t][idx] = 1.0f / fmaxf(sqrtf(ss), EPSF);
    } else if (blk < 4160) {
        int i = (blk - 4096) * 256 + threadIdx.x;   // i = l*128 + k
        int l = i >> 7, k = i & 127;
        float w = wm[k * NH + l];
        g_W2T[i] = w * w;
    } else {
        int i = (blk - 4160) * 256 + threadIdx.x;   // 65536 float4 = 262144 floats
        ((float4*)g_M)[i] = make_float4(0.f, 0.f, 0.f, 0.f);
    }
}

// ------------------------------------------------------------------
// M build: split-K SYRK-like, chunk=128 rows, atomicAdd accumulate.
// grid = 2*8*16 = 256 blocks, 256 threads. Inner product via f32x2.
// ------------------------------------------------------------------
__global__ __launch_bounds__(256) void mbuild_kernel(
    const float* __restrict__ h1, const float* __restrict__ h2)
{
    __shared__ float hs[32 * NH];
    __shared__ float sinv[32];
    int c = blockIdx.x & 15;
    int b = (blockIdx.x >> 4) & 7;
    int t = blockIdx.x >> 7;
    const float* src = t ? h2 : h1;
    const float* invp = g_inv[t] + b * NN;
    int tid = threadIdx.x;
    int tx = tid & 15, ty = tid >> 4;
    int k0 = tx * 4, l0 = ty * 4;

    // acc2[i][jp]: i = l index (0..3 -> l0+i, 4..7 -> l0+64+(i-4)),
    // jp = packed pair over k: jp0=(k0,k0+1), jp1=(k0+2,k0+3),
    //                          jp2=(k0+64,k0+65), jp3=(k0+66,k0+67)
    u64 acc2[8][4];
    #pragma unroll
    for (int i = 0; i < 8; i++)
        #pragma unroll
        for (int j = 0; j < 4; j++) acc2[i][j] = 0ull;

    int rowbase = c * 128;
    for (int sub = 0; sub < 4; sub++) {
        int rb = rowbase + sub * 32;
        __syncthreads();
        const float4* g = (const float4*)(src + ((size_t)b * NN + rb) * NH);
        float4* s4 = (float4*)hs;
        #pragma unroll
        for (int i = 0; i < 4; i++) s4[tid + 256 * i] = g[tid + 256 * i];
        if (tid < 32) sinv[tid] = invp[rb + tid];
        __syncthreads();

        #pragma unroll 4
        for (int m = 0; m < 32; m++) {
            float s = sinv[m];
            float4 la = *(const float4*)&hs[m * NH + l0];
            float4 lb = *(const float4*)&hs[m * NH + l0 + 64];
            ulonglong2 ka2 = *(const ulonglong2*)&hs[m * NH + k0];        // (k0,k0+1),(k0+2,k0+3)
            ulonglong2 kb2 = *(const ulonglong2*)&hs[m * NH + k0 + 64];   // (+64,+65),(+66,+67)
            float lv[8] = {la.x * s, la.y * s, la.z * s, la.w * s,
                           lb.x * s, lb.y * s, lb.z * s, lb.w * s};
            #pragma unroll
            for (int i = 0; i < 8; i++) {
                u64 bi = bcast2(lv[i]);
                fma2(acc2[i][0], bi, ka2.x);
                fma2(acc2[i][1], bi, ka2.y);
                fma2(acc2[i][2], bi, kb2.x);
                fma2(acc2[i][3], bi, kb2.y);
            }
        }
    }

    float* Mp = g_M[t][b];
    #pragma unroll
    for (int i = 0; i < 8; i++) {
        int l = l0 + ((i < 4) ? i : 60 + i);
        #pragma unroll
        for (int jp = 0; jp < 4; jp++) {
            float v0, v1;
            unpack2(acc2[i][jp], v0, v1);
            int kbase = k0 + ((jp < 2) ? jp * 2 : 64 + (jp - 2) * 2);
            atomicAdd(&Mp[l * NH + kbase + 0], v0);
            atomicAdd(&Mp[l * NH + kbase + 1], v1);
        }
    }
}

// ------------------------------------------------------------------
// fused fm: per 32-row tile of (t, b), GEMM phases in packed f32x2:
//   phase 1: y = (x @ M_{1-t}) * inv_t[row]
//   build   : u = x*y, a = x*x, c = y*y  (smem)
//   phase 2: NUM = u@W2T, DXX = a@W2T, DYY = c@W2T  (shared B tile)
//   epilogue: out = NUM / (max(sqrt(DXX),eps)*max(sqrt(DYY),eps))
// grid = 2*8*64 = 1024 blocks, 256 threads, 208 KB dynamic smem.
// ------------------------------------------------------------------
__global__ __launch_bounds__(256, 1) void fm_kernel(
    const float* __restrict__ h1, const float* __restrict__ h2,
    float* __restrict__ out)
{
    extern __shared__ float smem[];
    float* Ms  = smem;              // 16384 floats
    float* Ws  = smem + 16384;      // 16384
    float* xs  = smem + 32768;      // 4096
    float* ys  = smem + 36864;      // 4096
    float* us  = smem + 40960;      // 4096
    float* as_ = smem + 45056;      // 4096
    float* cs  = smem + 49152;      // 4096  -> total 53248 floats = 212992 B

    int rt = blockIdx.x & 63;
    int b  = (blockIdx.x >> 6) & 7;
    int t  = blockIdx.x >> 9;
    const float* src = t ? h2 : h1;
    const float* Mg = g_M[1 - t][b];
    int tid = threadIdx.x;

    // fill smem: M tile, W2T tile, x rows
    {
        const float4* mg4 = (const float4*)Mg;
        const float4* wg4 = (const float4*)g_W2T;
        float4* ms4 = (float4*)Ms;
        float4* ws4 = (float4*)Ws;
        #pragma unroll
        for (int i = 0; i < 16; i++) {
            ms4[tid + 256 * i] = mg4[tid + 256 * i];
            ws4[tid + 256 * i] = wg4[tid + 256 * i];
        }
        const float4* xg = (const float4*)(src + ((size_t)b * NN + rt * 32) * NH);
        float4* xs4 = (float4*)xs;
        #pragma unroll
        for (int i = 0; i < 4; i++) xs4[tid + 256 * i] = xg[tid + 256 * i];
    }
    __syncthreads();

    int tx = tid & 31, ty = tid >> 5;
    int k0 = tx * 4;
    int r0 = ty * 4;

    // ---- phase 1: y = x @ M (packed pairs over k: (k0,k0+1),(k0+2,k0+3)) ----
    u64 A1[4][2];
    #pragma unroll
    for (int r = 0; r < 4; r++) { A1[r][0] = 0ull; A1[r][1] = 0ull; }

    #pragma unroll 4
    for (int l = 0; l < NH; l += 4) {
        ulonglong2 w0 = *(const ulonglong2*)&Ms[(l + 0) * NH + k0];
        ulonglong2 w1 = *(const ulonglong2*)&Ms[(l + 1) * NH + k0];
        ulonglong2 w2 = *(const ulonglong2*)&Ms[(l + 2) * NH + k0];
        ulonglong2 w3 = *(const ulonglong2*)&Ms[(l + 3) * NH + k0];
        #pragma unroll
        for (int r = 0; r < 4; r++) {
            float4 xv = *(const float4*)&xs[(r0 + r) * NH + l];
            u64 bx = bcast2(xv.x), by = bcast2(xv.y), bz = bcast2(xv.z), bw = bcast2(xv.w);
            fma2(A1[r][0], bx, w0.x); fma2(A1[r][1], bx, w0.y);
            fma2(A1[r][0], by, w1.x); fma2(A1[r][1], by, w1.y);
            fma2(A1[r][0], bz, w2.x); fma2(A1[r][1], bz, w2.y);
            fma2(A1[r][0], bw, w3.x); fma2(A1[r][1], bw, w3.y);
        }
    }
    const float* invp = g_inv[t] + b * NN + rt * 32;
    #pragma unroll
    for (int r = 0; r < 4; r++) {
        float s = invp[r0 + r];
        float y0, y1, y2, y3;
        unpack2(A1[r][0], y0, y1);
        unpack2(A1[r][1], y2, y3);
        *(float4*)&ys[(r0 + r) * NH + k0] = make_float4(y0 * s, y1 * s, y2 * s, y3 * s);
    }
    __syncthreads();

    // ---- build u, a, c tiles ----
    {
        const float4* x4 = (const float4*)xs;
        const float4* y4 = (const float4*)ys;
        float4* u4 = (float4*)us;
        float4* a4 = (float4*)as_;
        float4* c4 = (float4*)cs;
        #pragma unroll
        for (int i = 0; i < 4; i++) {
            int e = tid + 256 * i;
            float4 xv = x4[e], yv = y4[e];
            u4[e] = make_float4(xv.x * yv.x, xv.y * yv.y, xv.z * yv.z, xv.w * yv.w);
            a4[e] = make_float4(xv.x * xv.x, xv.y * xv.y, xv.z * xv.z, xv.w * xv.w);
            c4[e] = make_float4(yv.x * yv.x, yv.y * yv.y, yv.z * yv.z, yv.w * yv.w);
        }
    }
    __syncthreads();

    // ---- phase 2: three GEMMs sharing W2T, packed pairs over k ----
    u64 AN[4][2], AA[4][2], AC[4][2];
    #pragma unroll
    for (int r = 0; r < 4; r++) {
        AN[r][0] = AN[r][1] = 0ull;
        AA[r][0] = AA[r][1] = 0ull;
        AC[r][0] = AC[r][1] = 0ull;
    }

    #pragma unroll 2
    for (int l = 0; l < NH; l += 4) {
        ulonglong2 w0 = *(const ulonglong2*)&Ws[(l + 0) * NH + k0];
        ulonglong2 w1 = *(const ulonglong2*)&Ws[(l + 1) * NH + k0];
        ulonglong2 w2 = *(const ulonglong2*)&Ws[(l + 2) * NH + k0];
        ulonglong2 w3 = *(const ulonglong2*)&Ws[(l + 3) * NH + k0];
        #pragma unroll
        for (int r = 0; r < 4; r++) {
            float4 uv = *(const float4*)&us[(r0 + r) * NH + l];
            float4 av = *(const float4*)&as_[(r0 + r) * NH + l];
            float4 cv = *(const float4*)&cs[(r0 + r) * NH + l];

            u64 p;
            p = bcast2(uv.x); fma2(AN[r][0], p, w0.x); fma2(AN[r][1], p, w0.y);
            p = bcast2(uv.y); fma2(AN[r][0], p, w1.x); fma2(AN[r][1], p, w1.y);
            p = bcast2(uv.z); fma2(AN[r][0], p, w2.x); fma2(AN[r][1], p, w2.y);
            p = bcast2(uv.w); fma2(AN[r][0], p, w3.x); fma2(AN[r][1], p, w3.y);

            p = bcast2(av.x); fma2(AA[r][0], p, w0.x); fma2(AA[r][1], p, w0.y);
            p = bcast2(av.y); fma2(AA[r][0], p, w1.x); fma2(AA[r][1], p, w1.y);
            p = bcast2(av.z); fma2(AA[r][0], p, w2.x); fma2(AA[r][1], p, w2.y);
            p = bcast2(av.w); fma2(AA[r][0], p, w3.x); fma2(AA[r][1], p, w3.y);

            p = bcast2(cv.x); fma2(AC[r][0], p, w0.x); fma2(AC[r][1], p, w0.y);
            p = bcast2(cv.y); fma2(AC[r][0], p, w1.x); fma2(AC[r][1], p, w1.y);
            p = bcast2(cv.z); fma2(AC[r][0], p, w2.x); fma2(AC[r][1], p, w2.y);
            p = bcast2(cv.w); fma2(AC[r][0], p, w3.x); fma2(AC[r][1], p, w3.y);
        }
    }

    // ---- epilogue ----
    float* op = out + (((size_t)t * NB + b) * NN + rt * 32) * NH;
    #pragma unroll
    for (int r = 0; r < 4; r++) {
        float n0, n1, n2, n3, a0, a1v, a2, a3, c0, c1, c2, c3;
        unpack2(AN[r][0], n0, n1); unpack2(AN[r][1], n2, n3);
        unpack2(AA[r][0], a0, a1v); unpack2(AA[r][1], a2, a3);
        unpack2(AC[r][0], c0, c1); unpack2(AC[r][1], c2, c3);
        float4 o;
        float d;
        d = fmaxf(sqrtf(a0),  EPSF) * fmaxf(sqrtf(c0), EPSF); o.x = n0 / d;
        d = fmaxf(sqrtf(a1v), EPSF) * fmaxf(sqrtf(c1), EPSF); o.y = n1 / d;
        d = fmaxf(sqrtf(a2),  EPSF) * fmaxf(sqrtf(c2), EPSF); o.z = n2 / d;
        d = fmaxf(sqrtf(a3),  EPSF) * fmaxf(sqrtf(c3), EPSF); o.w = n3 / d;
        *(float4*)&op[(r0 + r) * NH + k0] = o;
    }
}

extern "C" void kernel_launch(void* const* d_in, const int* in_sizes, int n_in,
                              void* d_out, int out_size) {
    const float* h1 = (const float*)d_in[0];
    const float* h2 = (const float*)d_in[1];
    const float* wm = (const float*)d_in[2];
    float* out = (float*)d_out;

    cudaFuncSetAttribute(fm_kernel, cudaFuncAttributeMaxDynamicSharedMemorySize, 212992);

    prep_kernel<<<4416, 256>>>(h1, h2, wm);
    mbuild_kernel<<<256, 256>>>(h1, h2);
    fm_kernel<<<1024, 256, 212992>>>(h1, h2, out);
}